// round 7
// baseline (speedup 1.0000x reference)
#include <cuda_runtime.h>
#include <cstdint>

// BlockDecomposition RGCN, GB300 sm_103a — gather formulation.
// out[t] = mask[t]*(xb[t] @ W[16]) + sum over incoming directed edges (s,r,w): w*(xb[s] @ W[r])
// Directed edges = both orientations of each input edge (symmetrized).
// Build: count degrees -> exclusive scan -> fill records sorted by target.
// Gather: warp per target, all-relation weight bank in registers, register accumulation, one store.

#define BS 4
#define DIM 128
#define BLK_STRIDE 512        // floats per relation
#define NUM_REL 16
#define NUM_REL_TOT 17
#define MAX_NODES 10048
#define MAX_DIRS  320000      // 2 * N_EDGES

// Transposed weights: g_wt[r*512 + i*128 + b*4 + j] = blocks[r][b][i][j]
__device__ float g_wt[NUM_REL_TOT * BLK_STRIDE];
__device__ int   g_deg[MAX_NODES];
__device__ int   g_off[MAX_NODES];
__device__ int   g_cur[MAX_NODES];
__device__ int4  g_rec[MAX_DIRS];   // {src, rel, w_bits, pad}

__device__ __forceinline__ float4 block_mm(float4 xv, float4 w0, float4 w1, float4 w2, float4 w3) {
    float4 m;
    m.x = fmaf(xv.x, w0.x, fmaf(xv.y, w1.x, fmaf(xv.z, w2.x, xv.w * w3.x)));
    m.y = fmaf(xv.x, w0.y, fmaf(xv.y, w1.y, fmaf(xv.z, w2.y, xv.w * w3.y)));
    m.z = fmaf(xv.x, w0.z, fmaf(xv.y, w1.z, fmaf(xv.z, w2.z, xv.w * w3.z)));
    m.w = fmaf(xv.x, w0.w, fmaf(xv.y, w1.w, fmaf(xv.z, w2.w, xv.w * w3.w)));
    return m;
}

// K1: zero degree counters + transpose weights into g_wt.
__global__ void __launch_bounds__(256) init_kernel(const float* __restrict__ blocks, int n_nodes)
{
    if (blockIdx.x < NUM_REL_TOT) {
        int r = blockIdx.x;
        #pragma unroll
        for (int k = 0; k < 2; k++) {
            int idx = threadIdx.x + k * 256;     // 0..511
            int b = idx >> 4, i = (idx >> 2) & 3, j = idx & 3;
            g_wt[r * BLK_STRIDE + i * 128 + b * 4 + j] = blocks[r * BLK_STRIDE + idx];
        }
    }
    int gid = blockIdx.x * 256 + threadIdx.x;
    if (gid < n_nodes) g_deg[gid] = 0;
}

// K2: count incoming directed edges per node (both orientations).
__global__ void __launch_bounds__(256) count_kernel(
    const int* __restrict__ src, const int* __restrict__ tgt, int n_edges)
{
    int e = blockIdx.x * 256 + threadIdx.x;
    if (e >= n_edges) return;
    atomicAdd(&g_deg[tgt[e]], 1);
    atomicAdd(&g_deg[src[e]], 1);
}

// K3: exclusive scan of degrees -> offsets (single block, 1024 threads).
__global__ void __launch_bounds__(1024) scan_kernel(int n)
{
    __shared__ int s_wsum[32];
    __shared__ int s_total;
    __shared__ int s_carry;
    int tid = threadIdx.x, lane = tid & 31, wid = tid >> 5;
    if (tid == 0) s_carry = 0;
    __syncthreads();

    for (int base = 0; base < n; base += 1024) {
        int i = base + tid;
        int v = (i < n) ? g_deg[i] : 0;
        int incl = v;
        #pragma unroll
        for (int off = 1; off < 32; off <<= 1) {
            int u = __shfl_up_sync(0xFFFFFFFFu, incl, off);
            if (lane >= off) incl += u;
        }
        if (lane == 31) s_wsum[wid] = incl;
        __syncthreads();
        if (wid == 0) {
            int wv = s_wsum[lane];
            int wi = wv;
            #pragma unroll
            for (int off = 1; off < 32; off <<= 1) {
                int u = __shfl_up_sync(0xFFFFFFFFu, wi, off);
                if (lane >= off) wi += u;
            }
            s_wsum[lane] = wi - wv;             // exclusive warp offset
            if (lane == 31) s_total = wi;       // block total
        }
        __syncthreads();
        int excl = incl - v + s_wsum[wid] + s_carry;
        if (i < n) { g_off[i] = excl; g_cur[i] = excl; }
        __syncthreads();
        if (tid == 0) s_carry += s_total;
        __syncthreads();
    }
}

// K4: fill target-sorted records (both orientations per edge).
__global__ void __launch_bounds__(256) fill_kernel(
    const int* __restrict__ src, const int* __restrict__ tgt,
    const int* __restrict__ etype, const float* __restrict__ eweight, int n_edges)
{
    int e = blockIdx.x * 256 + threadIdx.x;
    if (e >= n_edges) return;
    int s = src[e], t = tgt[e], r = etype[e];
    int wb = __float_as_int(eweight[e]);
    int p1 = atomicAdd(&g_cur[t], 1);
    g_rec[p1] = make_int4(s, r, wb, 0);
    int p2 = atomicAdd(&g_cur[s], 1);
    g_rec[p2] = make_int4(t, r, wb, 0);
}

// K5: gather. One warp per target node (grid-stride). Lane b owns block b.
// All 17 relations' 4x4 blocks live in registers; switch on warp-uniform r.
#define DECLW(R) float4 w##R##_0, w##R##_1, w##R##_2, w##R##_3;
#define LOADW(R) { const float* _p = g_wt + (R) * BLK_STRIDE + lane * 4; \
    w##R##_0 = *reinterpret_cast<const float4*>(_p); \
    w##R##_1 = *reinterpret_cast<const float4*>(_p + 128); \
    w##R##_2 = *reinterpret_cast<const float4*>(_p + 256); \
    w##R##_3 = *reinterpret_cast<const float4*>(_p + 384); }
#define CASE_R(R) case R: mm = block_mm(xv, w##R##_0, w##R##_1, w##R##_2, w##R##_3); break;
#define APPLY(rec, xv4) do { \
    float4 mm; float4 xv = (xv4); \
    switch ((rec).y) { \
        CASE_R(0) CASE_R(1) CASE_R(2) CASE_R(3) CASE_R(4) CASE_R(5) CASE_R(6) CASE_R(7) \
        CASE_R(8) CASE_R(9) CASE_R(10) CASE_R(11) CASE_R(12) CASE_R(13) CASE_R(14) CASE_R(15) \
        default: mm = make_float4(0.f, 0.f, 0.f, 0.f); break; \
    } \
    float wg = __int_as_float((rec).z); \
    acc.x = fmaf(wg, mm.x, acc.x); \
    acc.y = fmaf(wg, mm.y, acc.y); \
    acc.z = fmaf(wg, mm.z, acc.z); \
    acc.w = fmaf(wg, mm.w, acc.w); \
} while (0)

__global__ void __launch_bounds__(256) gather_kernel(
    const float* __restrict__ x,
    const int* __restrict__ keep_mask,
    float* __restrict__ out,
    int n_nodes)
{
    int lane = threadIdx.x & 31;
    int warp = (blockIdx.x * 256 + threadIdx.x) >> 5;
    int n_warps = (gridDim.x * 256) >> 5;

    DECLW(0) DECLW(1) DECLW(2) DECLW(3) DECLW(4) DECLW(5) DECLW(6) DECLW(7)
    DECLW(8) DECLW(9) DECLW(10) DECLW(11) DECLW(12) DECLW(13) DECLW(14) DECLW(15)
    DECLW(16)
    LOADW(0) LOADW(1) LOADW(2) LOADW(3) LOADW(4) LOADW(5) LOADW(6) LOADW(7)
    LOADW(8) LOADW(9) LOADW(10) LOADW(11) LOADW(12) LOADW(13) LOADW(14) LOADW(15)
    LOADW(16)

    for (int t = warp; t < n_nodes; t += n_warps) {
        int beg = g_off[t];
        int deg = g_deg[t];
        int end = beg + deg;

        // self-loop (relation 16), masked
        float4 xt = *reinterpret_cast<const float4*>(x + (size_t)t * DIM + lane * BS);
        float4 acc = block_mm(xt, w16_0, w16_1, w16_2, w16_3);
        if (keep_mask[t] == 0) { acc.x = 0.f; acc.y = 0.f; acc.z = 0.f; acc.w = 0.f; }

        // incoming directed edges, batches of 4 (gathers issued before compute)
        for (int j = beg; j < end; j += 4) {
            int rem = end - j;
            int4 r0 = g_rec[j];
            int4 r1 = (rem > 1) ? g_rec[j + 1] : r0;
            int4 r2 = (rem > 2) ? g_rec[j + 2] : r0;
            int4 r3 = (rem > 3) ? g_rec[j + 3] : r0;
            float4 x0 = *reinterpret_cast<const float4*>(x + (size_t)r0.x * DIM + lane * BS);
            float4 x1 = *reinterpret_cast<const float4*>(x + (size_t)r1.x * DIM + lane * BS);
            float4 x2 = *reinterpret_cast<const float4*>(x + (size_t)r2.x * DIM + lane * BS);
            float4 x3 = *reinterpret_cast<const float4*>(x + (size_t)r3.x * DIM + lane * BS);
            APPLY(r0, x0);
            if (rem > 1) APPLY(r1, x1);
            if (rem > 2) APPLY(r2, x2);
            if (rem > 3) APPLY(r3, x3);
        }

        *reinterpret_cast<float4*>(out + (size_t)t * DIM + lane * BS) = acc;
    }
}

extern "C" void kernel_launch(void* const* d_in, const int* in_sizes, int n_in,
                              void* d_out, int out_size)
{
    const float* x      = (const float*)d_in[0];
    const int*   mask   = (const int*)d_in[1];
    const int*   src    = (const int*)d_in[2];
    const int*   tgt    = (const int*)d_in[3];
    const int*   etype  = (const int*)d_in[4];
    const float* ew     = (const float*)d_in[5];
    const float* blocks = (const float*)d_in[6];
    float*       out    = (float*)d_out;

    int n_nodes = in_sizes[0] / DIM;
    int n_edges = in_sizes[2];

    int grid_n = (n_nodes + 255) / 256;
    if (grid_n < NUM_REL_TOT) grid_n = NUM_REL_TOT;
    init_kernel<<<grid_n, 256>>>(blocks, n_nodes);

    int grid_e = (n_edges + 255) / 256;
    count_kernel<<<grid_e, 256>>>(src, tgt, n_edges);

    scan_kernel<<<1, 1024>>>(n_nodes);

    fill_kernel<<<grid_e, 256>>>(src, tgt, etype, ew, n_edges);

    // ~2368 warps: each preloads the 34KB weight bank once, handles ~4 targets
    gather_kernel<<<296, 256>>>(x, mask, out, n_nodes);
}

// round 8
// speedup vs baseline: 1.5330x; 1.5330x over previous
#include <cuda_runtime.h>
#include <cstdint>

// BlockDecomposition RGCN, GB300 sm_103a — gather formulation v2 (smem weights).
// out[t] = mask[t]*(xb[t] @ W[16]) + sum over incoming directed edges (s,r,w): w*(xb[s] @ W[r])
// Build: count -> scan -> fill (target-sorted packed records). Gather: warp per target,
// smem weight bank, register accumulation, zero atomics in hot loop.

#define BS 4
#define DIM 128
#define BLK_STRIDE 512        // floats per relation
#define NUM_REL 16
#define NUM_REL_TOT 17
#define MAX_NODES 10048
#define MAX_DIRS  320000      // 2 * N_EDGES

// Transposed weights: g_wt[r*512 + i*128 + b*4 + j] = blocks[r][b][i][j]
__device__ float g_wt[NUM_REL_TOT * BLK_STRIDE];
__device__ int   g_deg[MAX_NODES];
__device__ int   g_off[MAX_NODES];
__device__ int   g_cur[MAX_NODES];
__device__ int2  g_rec[MAX_DIRS];   // {src | rel<<20, w_bits}

__device__ __forceinline__ float4 block_mm(float4 xv, float4 w0, float4 w1, float4 w2, float4 w3) {
    float4 m;
    m.x = fmaf(xv.x, w0.x, fmaf(xv.y, w1.x, fmaf(xv.z, w2.x, xv.w * w3.x)));
    m.y = fmaf(xv.x, w0.y, fmaf(xv.y, w1.y, fmaf(xv.z, w2.y, xv.w * w3.y)));
    m.z = fmaf(xv.x, w0.z, fmaf(xv.y, w1.z, fmaf(xv.z, w2.z, xv.w * w3.z)));
    m.w = fmaf(xv.x, w0.w, fmaf(xv.y, w1.w, fmaf(xv.z, w2.w, xv.w * w3.w)));
    return m;
}

// K1: zero degree counters + transpose weights into g_wt.
__global__ void __launch_bounds__(256) init_kernel(const float* __restrict__ blocks, int n_nodes)
{
    if (blockIdx.x < NUM_REL_TOT) {
        int r = blockIdx.x;
        #pragma unroll
        for (int k = 0; k < 2; k++) {
            int idx = threadIdx.x + k * 256;     // 0..511
            int b = idx >> 4, i = (idx >> 2) & 3, j = idx & 3;
            g_wt[r * BLK_STRIDE + i * 128 + b * 4 + j] = blocks[r * BLK_STRIDE + idx];
        }
    }
    int gid = blockIdx.x * 256 + threadIdx.x;
    if (gid < n_nodes) g_deg[gid] = 0;
}

// K2: count incoming directed edges per node (return-less atomics -> RED).
__global__ void __launch_bounds__(256) count_kernel(
    const int* __restrict__ src, const int* __restrict__ tgt, int n_edges)
{
    int e = blockIdx.x * 256 + threadIdx.x;
    if (e >= n_edges) return;
    atomicAdd(&g_deg[tgt[e]], 1);
    atomicAdd(&g_deg[src[e]], 1);
}

// K3: exclusive scan of degrees -> offsets (single block, 1024 threads).
__global__ void __launch_bounds__(1024) scan_kernel(int n)
{
    __shared__ int s_wsum[32];
    __shared__ int s_total;
    __shared__ int s_carry;
    int tid = threadIdx.x, lane = tid & 31, wid = tid >> 5;
    if (tid == 0) s_carry = 0;
    __syncthreads();

    for (int base = 0; base < n; base += 1024) {
        int i = base + tid;
        int v = (i < n) ? g_deg[i] : 0;
        int incl = v;
        #pragma unroll
        for (int off = 1; off < 32; off <<= 1) {
            int u = __shfl_up_sync(0xFFFFFFFFu, incl, off);
            if (lane >= off) incl += u;
        }
        if (lane == 31) s_wsum[wid] = incl;
        __syncthreads();
        if (wid == 0) {
            int wv = s_wsum[lane];
            int wi = wv;
            #pragma unroll
            for (int off = 1; off < 32; off <<= 1) {
                int u = __shfl_up_sync(0xFFFFFFFFu, wi, off);
                if (lane >= off) wi += u;
            }
            s_wsum[lane] = wi - wv;             // exclusive warp offset
            if (lane == 31) s_total = wi;       // block total
        }
        __syncthreads();
        int excl = incl - v + s_wsum[wid] + s_carry;
        if (i < n) { g_off[i] = excl; g_cur[i] = excl; }
        __syncthreads();
        if (tid == 0) s_carry += s_total;
        __syncthreads();
    }
}

// K4: fill target-sorted packed records. One thread per DIRECTION (2 per edge).
__global__ void __launch_bounds__(256) fill_kernel(
    const int* __restrict__ src, const int* __restrict__ tgt,
    const int* __restrict__ etype, const float* __restrict__ eweight, int n_edges)
{
    int gid = blockIdx.x * 256 + threadIdx.x;
    if (gid >= 2 * n_edges) return;
    int e = gid >> 1;
    int s = src[e], t = tgt[e];
    int node  = (gid & 1) ? s : t;    // record lands in this node's segment
    int other = (gid & 1) ? t : s;    // message source
    int r = etype[e];
    int wb = __float_as_int(eweight[e]);
    int pos = atomicAdd(&g_cur[node], 1);
    g_rec[pos] = make_int2(other | (r << 20), wb);
}

// K5: gather. Warp per target (grid-stride), weight bank in smem, batch-4 prefetch.
#define APPLY(pk, wbits, xv4) do { \
    int _r = (pk) >> 20; \
    const float* _wb = s_w + _r * BLK_STRIDE + lane * 4; \
    float4 _w0 = *reinterpret_cast<const float4*>(_wb); \
    float4 _w1 = *reinterpret_cast<const float4*>(_wb + 128); \
    float4 _w2 = *reinterpret_cast<const float4*>(_wb + 256); \
    float4 _w3 = *reinterpret_cast<const float4*>(_wb + 384); \
    float4 _mm = block_mm((xv4), _w0, _w1, _w2, _w3); \
    float _wg = __int_as_float(wbits); \
    acc.x = fmaf(_wg, _mm.x, acc.x); \
    acc.y = fmaf(_wg, _mm.y, acc.y); \
    acc.z = fmaf(_wg, _mm.z, acc.z); \
    acc.w = fmaf(_wg, _mm.w, acc.w); \
} while (0)

__global__ void __launch_bounds__(256) gather_kernel(
    const float* __restrict__ x,
    const int* __restrict__ keep_mask,
    float* __restrict__ out,
    int n_nodes)
{
    __shared__ float s_w[NUM_REL_TOT * BLK_STRIDE];   // 34 KB weight bank
    for (int i = threadIdx.x; i < NUM_REL_TOT * BLK_STRIDE; i += 256)
        s_w[i] = g_wt[i];
    __syncthreads();

    int lane = threadIdx.x & 31;
    int warp = (blockIdx.x * 256 + threadIdx.x) >> 5;
    int n_warps = (gridDim.x * 256) >> 5;

    // self-loop weights (relation 16) hoisted to registers
    const float* swb = s_w + 16 * BLK_STRIDE + lane * 4;
    float4 sw0 = *reinterpret_cast<const float4*>(swb);
    float4 sw1 = *reinterpret_cast<const float4*>(swb + 128);
    float4 sw2 = *reinterpret_cast<const float4*>(swb + 256);
    float4 sw3 = *reinterpret_cast<const float4*>(swb + 384);

    for (int t = warp; t < n_nodes; t += n_warps) {
        int beg = g_off[t];
        int end = beg + g_deg[t];

        float4 xt = *reinterpret_cast<const float4*>(x + (size_t)t * DIM + lane * BS);
        float4 acc = block_mm(xt, sw0, sw1, sw2, sw3);
        if (keep_mask[t] == 0) { acc.x = 0.f; acc.y = 0.f; acc.z = 0.f; acc.w = 0.f; }

        for (int j = beg; j < end; j += 4) {
            int rem = end - j;
            int2 r0 = g_rec[j];
            int2 r1 = (rem > 1) ? g_rec[j + 1] : r0;
            int2 r2 = (rem > 2) ? g_rec[j + 2] : r0;
            int2 r3 = (rem > 3) ? g_rec[j + 3] : r0;
            float4 x0 = *reinterpret_cast<const float4*>(x + (size_t)(r0.x & 0xFFFFF) * DIM + lane * BS);
            float4 x1 = *reinterpret_cast<const float4*>(x + (size_t)(r1.x & 0xFFFFF) * DIM + lane * BS);
            float4 x2 = *reinterpret_cast<const float4*>(x + (size_t)(r2.x & 0xFFFFF) * DIM + lane * BS);
            float4 x3 = *reinterpret_cast<const float4*>(x + (size_t)(r3.x & 0xFFFFF) * DIM + lane * BS);
            APPLY(r0.x, r0.y, x0);
            if (rem > 1) APPLY(r1.x, r1.y, x1);
            if (rem > 2) APPLY(r2.x, r2.y, x2);
            if (rem > 3) APPLY(r3.x, r3.y, x3);
        }

        *reinterpret_cast<float4*>(out + (size_t)t * DIM + lane * BS) = acc;
    }
}

extern "C" void kernel_launch(void* const* d_in, const int* in_sizes, int n_in,
                              void* d_out, int out_size)
{
    const float* x      = (const float*)d_in[0];
    const int*   mask   = (const int*)d_in[1];
    const int*   src    = (const int*)d_in[2];
    const int*   tgt    = (const int*)d_in[3];
    const int*   etype  = (const int*)d_in[4];
    const float* ew     = (const float*)d_in[5];
    const float* blocks = (const float*)d_in[6];
    float*       out    = (float*)d_out;

    int n_nodes = in_sizes[0] / DIM;
    int n_edges = in_sizes[2];

    int grid_n = (n_nodes + 255) / 256;
    if (grid_n < NUM_REL_TOT) grid_n = NUM_REL_TOT;
    init_kernel<<<grid_n, 256>>>(blocks, n_nodes);

    int grid_e = (n_edges + 255) / 256;
    count_kernel<<<grid_e, 256>>>(src, tgt, n_edges);

    scan_kernel<<<1, 1024>>>(n_nodes);

    int grid_f = (2 * n_edges + 255) / 256;
    fill_kernel<<<grid_f, 256>>>(src, tgt, etype, ew, n_edges);

    // 148 SMs x 4 blocks: 4736 warps, ~2.1 targets/warp
    gather_kernel<<<592, 256>>>(x, mask, out, n_nodes);
}